// round 7
// baseline (speedup 1.0000x reference)
#include <cuda_runtime.h>
#include <cstdint>

// Problem dims
#define BB      128
#define TT      512
#define UU      128
#define NW      80          // N (window/transcription feature dim)
#define HH      512
#define MM      10
#define KSTAGE  592         // staged rows: 0..511 = h, 512..591 = w
#define NKK     298         // packed-pair K rows: 2 (x0,x1 / x2,pad) + 296 staged
#define GRID    128
#define BLOCK   512
#define OUT_STRIDE 593      // H + NW + 1
#define CHUNK   64
#define NCHUNK  10          // 9*64 + 16
#define SIN_STRIDE 68       // floats per batch-row per stage (64 + 4 pad)
#define SIN_STAGE (BB * SIN_STRIDE)   // 8704 floats per stage

// ---------------- device global state (no allocations allowed) ----------------
// g_inp[buf][b][row]: per-batch contiguous. rows 0..511 = h, 512..591 = w.
__device__ float g_inp[2 * BB * KSTAGE];
__device__ float g_kappa[BB * MM];
__device__ unsigned int g_bar;
__device__ unsigned int g_wdone;

// ---------------- helpers ----------------
__device__ __forceinline__ unsigned long long pack2(float x, float y) {
    unsigned long long r;
    asm("mov.b64 %0, {%1, %2};" : "=l"(r) : "f"(x), "f"(y));
    return r;
}
__device__ __forceinline__ void unpack2(unsigned long long v, float &lo, float &hi) {
    asm("mov.b64 {%0, %1}, %2;" : "=f"(lo), "=f"(hi) : "l"(v));
}
// packed fp32x2 FMA (sm_100+): d = a*b + d, lane-wise
__device__ __forceinline__ void ffma2(unsigned long long &d, unsigned long long a, unsigned long long b) {
    asm("fma.rn.f32x2 %0, %1, %2, %0;" : "+l"(d) : "l"(a), "l"(b));
}
__device__ __forceinline__ float sigf(float x) {
    return __fdividef(1.f, 1.f + __expf(-x));
}

__device__ __forceinline__ void grid_barrier(unsigned int target) {
    __threadfence();              // release
    __syncthreads();
    if (threadIdx.x == 0) {
        atomicAdd(&g_bar, 1u);
        volatile unsigned int* vp = &g_bar;
        while (*vp < target) { }
        __threadfence();          // acquire
    }
    __syncthreads();
}

// ---------------- init kernel (reset state every replay) ----------------
__global__ void rnn_init_kernel() {
    int tid = blockIdx.x * blockDim.x + threadIdx.x;
    int nthr = gridDim.x * blockDim.x;
    for (int i = tid; i < 2 * BB * KSTAGE; i += nthr) g_inp[i] = 0.f;
    for (int i = tid; i < BB * MM;         i += nthr) g_kappa[i] = 0.f;
    if (tid == 0) { g_bar = 0u; g_wdone = 0u; }
}

// ---------------- shared memory layout (dynamic) ----------------
#define OFF_WP   0                       // NKK*32 floats = 38144 B (packed-pair weights)
#define OFF_WD   38144                   // 512*30 floats = 61440 B
#define OFF_TR   99584                   // 128*80 floats = 40960 B
#define OFF_IN   140544                  // 2*8704 floats = 69632 B (staging)
#define OFF_H    210176                  // 512 floats    = 2048 B
#define OFF_YP   212224                  // 480 floats    = 1920 B
#define OFF_WF   214144                  // 136 floats    = 544 B
#define OFF_Y    214688                  // 32 floats     = 128 B
#define OFF_BD   214816                  // 32 floats     = 128 B
#define OFF_A    214944                  // 16 floats     = 64 B
#define OFF_BE   215008                  // 16 floats     = 64 B
#define OFF_KA   215072                  // 16 floats     = 64 B
#define OFF_BIAS 215136                  // 16 floats     = 64 B
#define SMEM_BYTES 215200

extern __shared__ char smem_raw[];

// copy one chunk (rows [base, base+rows) of all 128 b) into staging buffer,
// with XOR swizzle of the 16B group index to kill LDS bank conflicts:
// group q of batch b lands at slot q ^ ((b>>3)&3)  (stays within 64B window).
__device__ __forceinline__ void prefetch_chunk(const float* gsrc /* gin + base */,
                                               uint32_t sdst, int lg /*log2(rows/4)*/,
                                               int tid) {
    const int nq = 1 << lg;
    const int tot = BB << lg;
    for (int i = tid; i < tot; i += BLOCK) {
        int bb_ = i >> lg, q = i & (nq - 1);
        int qs = q ^ ((bb_ >> 3) & 3);
        asm volatile("cp.async.cg.shared.global [%0], [%1], 16;"
                     :: "r"(sdst + bb_ * (SIN_STRIDE * 4) + qs * 16),
                        "l"(gsrc + (size_t)bb_ * KSTAGE + q * 4));
    }
    asm volatile("cp.async.commit_group;");
}

__global__ void __launch_bounds__(BLOCK, 1)
rnn_persistent_kernel(const float* __restrict__ strokes,
                      const float* __restrict__ trans,
                      const float* __restrict__ Wx,
                      const float* __restrict__ Wh,
                      const float* __restrict__ bvec,
                      const float* __restrict__ Wd,
                      const float* __restrict__ bd,
                      float* __restrict__ out) {
    float* sWp   = (float*)(smem_raw + OFF_WP);    // [NKK][4 grp][4 gate][2 lane]
    float* sWd   = (float*)(smem_raw + OFF_WD);    // [512][30]
    float* sTr   = (float*)(smem_raw + OFF_TR);    // [128][80]
    float* sIn   = (float*)(smem_raw + OFF_IN);    // [2][128][68] staging (swizzled)
    float* s_h   = (float*)(smem_raw + OFF_H);     // [512]
    float* s_yp  = (float*)(smem_raw + OFF_YP);    // [480]
    float* s_wf  = (float*)(smem_raw + OFF_WF);    // [129]
    float* s_y   = (float*)(smem_raw + OFF_Y);     // [30]
    float* s_bd  = (float*)(smem_raw + OFF_BD);    // [30]
    float* s_a   = (float*)(smem_raw + OFF_A);     // [10]
    float* s_be  = (float*)(smem_raw + OFF_BE);    // [10]
    float* s_ka  = (float*)(smem_raw + OFF_KA);    // [10]
    float* sBias = (float*)(smem_raw + OFF_BIAS);  // [4 grp][4 gate]

    const uint32_t sIn32 = (uint32_t)__cvta_generic_to_shared(sIn);

    const int tid = threadIdx.x;
    const int b   = tid & 127;           // batch row (GEMM phase)
    const int grp = tid >> 7;            // which of the CTA's 4 h-columns
    const int swz = (b >> 3) & 3;        // bank-conflict swizzle for this lane
    const int bb  = blockIdx.x;          // CTA == batch row in attention phase
    const int j0  = blockIdx.x * 4;      // owned h-columns [j0, j0+4)

    // ---- one-time staging ----
    // sWp[kk][grp][gate][lane]: lane 0 = even-k weight, lane 1 = odd-k weight.
    // kk 0: k=(x0,x1); kk 1: k=(x2, zero-pad); kk>=2: staged rows s=2(kk-2)+lane
    //   (s<512 -> Wh row s; else -> Wx row 3+(s-512), i.e. the w inputs).
    for (int i = tid; i < NKK * 32; i += BLOCK) {
        int kk = i >> 5, rem = i & 31;
        int g_ = rem >> 3, e = rem & 7, gate = e >> 1, lane = e & 1;
        int col = (gate << 9) + j0 + g_;
        float val;
        if (kk >= 2) {
            int s = 2 * (kk - 2) + lane;
            val = (s < HH) ? Wh[s * 2048 + col] : Wx[(3 + s - HH) * 2048 + col];
        } else {
            int k = kk * 2 + lane;
            val = (k < 3) ? Wx[k * 2048 + col] : 0.f;
        }
        sWp[i] = val;
    }
    if (tid < 16) {
        int g_ = tid >> 2, gate = tid & 3;
        sBias[tid] = bvec[(gate << 9) + j0 + g_];
    }
    for (int i = tid; i < HH * 30; i += BLOCK) sWd[i] = Wd[i];
    if (tid < 30) s_bd[tid] = bd[tid];
    for (int i = tid; i < UU * NW; i += BLOCK) sTr[i] = trans[bb * UU * NW + i];
    __syncthreads();

    float creg = 0.f;                    // c-state for this thread's column
    unsigned int tgt = 0;

    for (int t = 0; t < TT; ++t) {
        const float* __restrict__ gin = g_inp + (t & 1) * (BB * KSTAGE);

        // =========== Phase A: z for 4 gates of column j0+grp ===========
        unsigned long long a_i = pack2(sBias[grp * 4 + 0], 0.f);
        unsigned long long a_f = pack2(sBias[grp * 4 + 1], 0.f);
        unsigned long long a_g = pack2(sBias[grp * 4 + 2], 0.f);
        unsigned long long a_o = pack2(sBias[grp * 4 + 3], 0.f);

        // kick x loads early (consumed at the end of phase A)
        const float* xp = strokes + ((size_t)b * TT + t) * 3;
        float x0 = xp[0], x1 = xp[1], x2 = xp[2];

        // prime pipeline: chunks 0 and 1 (h rows — ready after last barrier)
        prefetch_chunk(gin,         sIn32,                  4, tid);
        prefetch_chunk(gin + CHUNK, sIn32 + SIN_STAGE * 4,  4, tid);

        const unsigned int wtarget = (unsigned int)t * GRID;

        for (int c = 0; c < NCHUNK; ++c) {
            const int rows = (c < NCHUNK - 1) ? CHUNK : 16;
            if (c < NCHUNK - 1) asm volatile("cp.async.wait_group 1;");
            else                asm volatile("cp.async.wait_group 0;");
            __syncthreads();

            const float* sb = sIn + (c & 1) * SIN_STAGE + b * SIN_STRIDE;
            // kk row for staged row 64c is 32c+2
            const ulonglong2* wbase =
                (const ulonglong2*)(sWp + (32 * c + 2) * 32 + grp * 8);
#pragma unroll 4
            for (int r = 0; r < rows; r += 4) {
                // swizzled, conflict-free 16B load of k pairs (r,r+1),(r+2,r+3)
                ulonglong2 vv = *(const ulonglong2*)(sb + ((((r >> 2) ^ swz)) << 2));
                const ulonglong2* w = wbase + r * 4;            // kk stride = 8 ulonglong2
                ulonglong2 wA0 = w[0], wA1 = w[1];              // kk   : (i,f),(g,o) pairs
                ulonglong2 wB0 = w[8], wB1 = w[9];              // kk+1
                ffma2(a_i, vv.x, wA0.x); ffma2(a_f, vv.x, wA0.y);
                ffma2(a_g, vv.x, wA1.x); ffma2(a_o, vv.x, wA1.y);
                ffma2(a_i, vv.y, wB0.x); ffma2(a_f, vv.y, wB0.y);
                ffma2(a_g, vv.y, wB1.x); ffma2(a_o, vv.y, wB1.y);
            }
            __syncthreads();
            if (c + 2 < NCHUNK) {
                if (c == 6) {
                    // chunks 8,9 carry w_{t-1}: wait for all CTAs' phase C(t-1).
                    if (tid == 0) {
                        volatile unsigned int* vp = &g_wdone;
                        while (*vp < wtarget) { }
                        __threadfence();
                    }
                    __syncthreads();
                }
                prefetch_chunk(gin + (c + 2) * CHUNK,
                               sIn32 + (c & 1) * (SIN_STAGE * 4),
                               (c + 2 < NCHUNK - 1) ? 4 : 2, tid);
            }
        }

        // x contribution (kk rows 0,1)
        {
            unsigned long long vx0 = pack2(x0, x1);
            unsigned long long vx1 = pack2(x2, 0.f);
            const ulonglong2* w0 = (const ulonglong2*)(sWp + grp * 8);
            const ulonglong2* w1 = (const ulonglong2*)(sWp + 32 + grp * 8);
            ulonglong2 wA0 = w0[0], wA1 = w0[1], wB0 = w1[0], wB1 = w1[1];
            ffma2(a_i, vx0, wA0.x); ffma2(a_f, vx0, wA0.y);
            ffma2(a_g, vx0, wA1.x); ffma2(a_o, vx0, wA1.y);
            ffma2(a_i, vx1, wB0.x); ffma2(a_f, vx1, wB0.y);
            ffma2(a_g, vx1, wB1.x); ffma2(a_o, vx1, wB1.y);
        }

        // =========== Phase B: LSTM pointwise update (1 column / thread) ===========
        {
            float lo, hi;
            unpack2(a_i, lo, hi); float zi = lo + hi;
            unpack2(a_f, lo, hi); float zf = lo + hi;
            unpack2(a_g, lo, hi); float zg = lo + hi;
            unpack2(a_o, lo, hi); float zo = lo + hi;

            float cn = sigf(zf) * creg + sigf(zi) * tanhf(zg);
            float hn = sigf(zo) * tanhf(cn); creg = cn;

            int col = j0 + grp;
            out[((size_t)b * TT + t) * OUT_STRIDE + col] = hn;
            g_inp[((t + 1) & 1) * (BB * KSTAGE) + (size_t)b * KSTAGE + col] = hn;
        }

        tgt += GRID;
        grid_barrier(tgt);   // all h_new visible (in out[] and next g_inp buf)

        // =========== Phase C: attention head for batch row bb ===========
        {
            float* orow = out + ((size_t)bb * TT + t) * OUT_STRIDE;

            s_h[tid] = orow[tid];       // BLOCK==HH: coalesced own-row h read
            __syncthreads();

            // y = h @ Wd  (30 outputs, 16-way K split over 480 threads)
            if (tid < 480) {
                int n = tid >> 4, q = tid & 15;
                int k0 = q * 32;
                float p0 = 0.f, p1 = 0.f, p2 = 0.f, p3 = 0.f;
#pragma unroll 4
                for (int k = k0; k < k0 + 32; k += 4) {
                    p0 = fmaf(s_h[k],     sWd[(k)     * 30 + n], p0);
                    p1 = fmaf(s_h[k + 1], sWd[(k + 1) * 30 + n], p1);
                    p2 = fmaf(s_h[k + 2], sWd[(k + 2) * 30 + n], p2);
                    p3 = fmaf(s_h[k + 3], sWd[(k + 3) * 30 + n], p3);
                }
                s_yp[tid] = (p0 + p1) + (p2 + p3);
            }
            __syncthreads();
            if (tid < 30) {
                float s = 0.f;
#pragma unroll
                for (int q = 0; q < 16; ++q) s += s_yp[tid * 16 + q];
                s_y[tid] = __expf(s + s_bd[tid]);
            }
            __syncthreads();
            if (tid < MM) {
                float ka = g_kappa[bb * MM + tid] + s_y[20 + tid];
                g_kappa[bb * MM + tid] = ka;
                s_ka[tid] = ka;
                s_a[tid]  = s_y[tid];
                s_be[tid] = s_y[10 + tid];
            }
            __syncthreads();

            // phi / wfull over u = 0..128
            if (tid <= UU) {
                float fu = (float)tid;
                float acc = 0.f;
#pragma unroll
                for (int m = 0; m < MM; ++m) {
                    float d = s_ka[m] - fu;
                    acc = fmaf(s_a[m], __expf(-s_be[m] * d * d), acc);
                }
                s_wf[tid] = acc;
            }
            __syncthreads();

            // argmax (first-max tie rule), warp 0
            if (tid < 32) {
                float bv = -3.4e38f; int bi = 0;
                for (int u = tid; u <= UU; u += 32) {
                    float v = s_wf[u];
                    if (v > bv) { bv = v; bi = u; }
                }
                for (int off = 16; off; off >>= 1) {
                    float ov = __shfl_xor_sync(0xffffffffu, bv, off);
                    int   oi = __shfl_xor_sync(0xffffffffu, bi, off);
                    if (ov > bv || (ov == bv && oi < bi)) { bv = ov; bi = oi; }
                }
                if (tid == 0) orow[HH + NW] = (float)bi;
            }

            // w = wfull[:U] @ transcriptions[bb]  (rows 512+ of g_inp[bb])
            if (tid < NW) {
                float a0 = 0.f, a1 = 0.f, a2 = 0.f, a3 = 0.f;
#pragma unroll 4
                for (int u = 0; u < UU; u += 4) {
                    a0 = fmaf(s_wf[u],     sTr[(u)     * NW + tid], a0);
                    a1 = fmaf(s_wf[u + 1], sTr[(u + 1) * NW + tid], a1);
                    a2 = fmaf(s_wf[u + 2], sTr[(u + 2) * NW + tid], a2);
                    a3 = fmaf(s_wf[u + 3], sTr[(u + 3) * NW + tid], a3);
                }
                float wv = (a0 + a1) + (a2 + a3);
                g_inp[((t + 1) & 1) * (BB * KSTAGE) + (size_t)bb * KSTAGE + HH + tid] = wv;
                orow[HH + tid] = wv;
            }

            __syncthreads();
            if (tid == 0) {            // signal w_t ready (consumed at chunk 8 of t+1)
                __threadfence();
                atomicAdd(&g_wdone, 1u);
            }
        }
    }
}

// ---------------- launch ----------------
extern "C" void kernel_launch(void* const* d_in, const int* in_sizes, int n_in,
                              void* d_out, int out_size) {
    const float* strokes = (const float*)d_in[0];
    const float* trans   = (const float*)d_in[1];
    // d_in[2] = enumerated (0..128) -- recomputed on the fly
    const float* Wx      = (const float*)d_in[3];
    const float* Wh      = (const float*)d_in[4];
    const float* bvec    = (const float*)d_in[5];
    const float* Wd      = (const float*)d_in[6];
    const float* bd      = (const float*)d_in[7];
    float* out = (float*)d_out;

    cudaFuncSetAttribute(rnn_persistent_kernel,
                         cudaFuncAttributeMaxDynamicSharedMemorySize, SMEM_BYTES);

    rnn_init_kernel<<<32, 256>>>();
    rnn_persistent_kernel<<<GRID, BLOCK, SMEM_BYTES>>>(strokes, trans, Wx, Wh,
                                                       bvec, Wd, bd, out);
}

// round 9
// speedup vs baseline: 1.1498x; 1.1498x over previous
#include <cuda_runtime.h>
#include <cstdint>

// Problem dims
#define BB      128
#define TT      512
#define UU      128
#define NW      80          // N (window/transcription feature dim)
#define HH      512
#define MM      10
#define NKK     322         // packed-pair K rows: 2 (x) + 320 staged (incl. pad)
#define GRID    128
#define BLOCK   512
#define OUT_STRIDE 593      // H + NW + 1
#define NCHUNK  10
#define CHUNKF  64          // floats per chunk per batch row
#define CHUNK_BYTES 32768   // 128 b * 64 f * 4 B
#define GBUF    (NCHUNK * BB * CHUNKF)   // 81920 floats per buffer

// ---------------- device global state (no allocations allowed) ----------------
// g_inp[buf][chunk][b][64]: chunk c holds staged k = 64c..64c+63.
// k 0..511 = h, 512..591 = w, 592..639 = permanent zero pad.
// Within each [b][64] row, 16B group q is stored at slot q ^ (b & 15)  (bank swizzle).
__device__ __align__(128) float g_inp[2 * GBUF];
__device__ float g_kappa[BB * MM];
__device__ unsigned int g_bar;
__device__ unsigned int g_wdone;

// ---------------- helpers ----------------
__device__ __forceinline__ unsigned long long pack2(float x, float y) {
    unsigned long long r;
    asm("mov.b64 %0, {%1, %2};" : "=l"(r) : "f"(x), "f"(y));
    return r;
}
__device__ __forceinline__ void unpack2(unsigned long long v, float &lo, float &hi) {
    asm("mov.b64 {%0, %1}, %2;" : "=f"(lo), "=f"(hi) : "l"(v));
}
// packed fp32x2 FMA (sm_100+): d = a*b + d, lane-wise
__device__ __forceinline__ void ffma2(unsigned long long &d, unsigned long long a, unsigned long long b) {
    asm("fma.rn.f32x2 %0, %1, %2, %0;" : "+l"(d) : "l"(a), "l"(b));
}
__device__ __forceinline__ float sigf(float x) {
    return __fdividef(1.f, 1.f + __expf(-x));
}

__device__ __forceinline__ void grid_barrier(unsigned int target) {
    __threadfence();              // release
    __syncthreads();
    if (threadIdx.x == 0) {
        atomicAdd(&g_bar, 1u);
        volatile unsigned int* vp = &g_bar;
        while (*vp < target) { }
        __threadfence();          // acquire
    }
    __syncthreads();
}

// single-thread bulk-DMA of one 32KB chunk into smem, completion on mbarrier
__device__ __forceinline__ void issue_chunk(uint32_t mbar, uint32_t sdst,
                                            const float* gsrc) {
    asm volatile("mbarrier.arrive.expect_tx.shared::cta.b64 _, [%0], %1;"
                 :: "r"(mbar), "r"(CHUNK_BYTES) : "memory");
    asm volatile("cp.async.bulk.shared::cta.global.mbarrier::complete_tx::bytes "
                 "[%0], [%1], %2, [%3];"
                 :: "r"(sdst), "l"(gsrc), "r"(CHUNK_BYTES), "r"(mbar) : "memory");
}

__device__ __forceinline__ void mbar_wait(uint32_t mbar, unsigned int parity) {
    asm volatile(
        "{\n\t"
        ".reg .pred P;\n\t"
        "LAB_%=:\n\t"
        "mbarrier.try_wait.parity.acquire.cta.shared::cta.b64 P, [%0], %1, 0x989680;\n\t"
        "@!P bra LAB_%=;\n\t"
        "}"
        :: "r"(mbar), "r"(parity) : "memory");
}

// ---------------- init kernel (reset state every replay) ----------------
__global__ void rnn_init_kernel() {
    int tid = blockIdx.x * blockDim.x + threadIdx.x;
    int nthr = gridDim.x * blockDim.x;
    for (int i = tid; i < 2 * GBUF; i += nthr) g_inp[i] = 0.f;
    for (int i = tid; i < BB * MM; i += nthr) g_kappa[i] = 0.f;
    if (tid == 0) { g_bar = 0u; g_wdone = 0u; }
}

// ---------------- shared memory layout (dynamic) ----------------
#define OFF_MBAR 0                       // 2 mbarriers, 16 B
#define OFF_WP   16                      // 322*32 floats = 41216 B
#define OFF_WD   41232                   // 512*30 floats = 61440 B
#define OFF_TR   102672                  // 128*80 floats = 40960 B
#define OFF_IN   143744                  // 2*8192 floats = 65536 B (128B aligned)
#define OFF_H    209280                  // 512 floats    = 2048 B
#define OFF_YP   211328                  // 480 floats    = 1920 B
#define OFF_WF   213248                  // 136 floats    = 544 B
#define OFF_Y    213792                  // 32 floats     = 128 B
#define OFF_BD   213920                  // 32 floats     = 128 B
#define OFF_A    214048                  // 16 floats     = 64 B
#define OFF_BE   214112                  // 16 floats     = 64 B
#define OFF_KA   214176                  // 16 floats     = 64 B
#define OFF_BIAS 214240                  // 16 floats     = 64 B
#define SMEM_BYTES 214304

extern __shared__ char smem_raw[];

__global__ void __launch_bounds__(BLOCK, 1)
rnn_persistent_kernel(const float* __restrict__ strokes,
                      const float* __restrict__ trans,
                      const float* __restrict__ Wx,
                      const float* __restrict__ Wh,
                      const float* __restrict__ bvec,
                      const float* __restrict__ Wd,
                      const float* __restrict__ bd,
                      float* __restrict__ out) {
    float* sWp   = (float*)(smem_raw + OFF_WP);    // [NKK][4 grp][4 gate][2 lane]
    float* sWd   = (float*)(smem_raw + OFF_WD);    // [512][30]
    float* sTr   = (float*)(smem_raw + OFF_TR);    // [128][80]
    float* sIn   = (float*)(smem_raw + OFF_IN);    // [2][128][64] staging
    float* s_h   = (float*)(smem_raw + OFF_H);     // [512]
    float* s_yp  = (float*)(smem_raw + OFF_YP);    // [480]
    float* s_wf  = (float*)(smem_raw + OFF_WF);    // [129]
    float* s_y   = (float*)(smem_raw + OFF_Y);     // [30]
    float* s_bd  = (float*)(smem_raw + OFF_BD);    // [30]
    float* s_a   = (float*)(smem_raw + OFF_A);     // [10]
    float* s_be  = (float*)(smem_raw + OFF_BE);    // [10]
    float* s_ka  = (float*)(smem_raw + OFF_KA);    // [10]
    float* sBias = (float*)(smem_raw + OFF_BIAS);  // [4 grp][4 gate]

    const uint32_t smem_base = (uint32_t)__cvta_generic_to_shared(smem_raw);
    const uint32_t mbar0 = smem_base + OFF_MBAR;
    const uint32_t mbar1 = smem_base + OFF_MBAR + 8;
    const uint32_t sIn32 = smem_base + OFF_IN;

    const int tid = threadIdx.x;
    const int b   = tid & 127;           // batch row (GEMM phase)
    const int grp = tid >> 7;            // which of the CTA's 4 h-columns
    const int bsw = b & 15;              // per-lane 16B-group swizzle key
    const int bb  = blockIdx.x;          // CTA == batch row in attention phase
    const int j0  = blockIdx.x * 4;      // owned h-columns [j0, j0+4)

    // ---- mbarrier init ----
    if (tid == 0) {
        asm volatile("mbarrier.init.shared.b64 [%0], 1;" :: "r"(mbar0) : "memory");
        asm volatile("mbarrier.init.shared.b64 [%0], 1;" :: "r"(mbar1) : "memory");
        asm volatile("fence.proxy.async.shared::cta;" ::: "memory");
    }

    // ---- one-time weight staging ----
    // sWp[kk][grp][gate][lane]: lane 0 = even-k weight, lane 1 = odd-k weight.
    // kk 0: k=(x0,x1); kk 1: k=(x2, pad); kk>=2: staged rows s=2(kk-2)+lane
    //   (s<512 -> Wh row s; s<592 -> Wx row 3+(s-512) (w inputs); else 0 pad).
    for (int i = tid; i < NKK * 32; i += BLOCK) {
        int kk = i >> 5, rem = i & 31;
        int g_ = rem >> 3, e = rem & 7, gate = e >> 1, lane = e & 1;
        int col = (gate << 9) + j0 + g_;
        float val;
        if (kk >= 2) {
            int s = 2 * (kk - 2) + lane;
            if (s < HH)            val = Wh[s * 2048 + col];
            else if (s < HH + NW)  val = Wx[(3 + s - HH) * 2048 + col];
            else                   val = 0.f;
        } else {
            int k = kk * 2 + lane;
            val = (k < 3) ? Wx[k * 2048 + col] : 0.f;
        }
        sWp[i] = val;
    }
    if (tid < 16) {
        int g_ = tid >> 2, gate = tid & 3;
        sBias[tid] = bvec[(gate << 9) + j0 + g_];
    }
    for (int i = tid; i < HH * 30; i += BLOCK) sWd[i] = Wd[i];
    if (tid < 30) s_bd[tid] = bd[tid];
    for (int i = tid; i < UU * NW; i += BLOCK) sTr[i] = trans[bb * UU * NW + i];
    __syncthreads();

    float creg = 0.f;                    // c-state for this thread's column
    unsigned int tgt = 0;

    for (int t = 0; t < TT; ++t) {
        const float* __restrict__ gin = g_inp + (t & 1) * GBUF;
        float* __restrict__ gnext = g_inp + ((t + 1) & 1) * GBUF;

        // =========== Phase A: z for 4 gates of column j0+grp ===========
        unsigned long long a_i = pack2(sBias[grp * 4 + 0], 0.f);
        unsigned long long a_f = pack2(sBias[grp * 4 + 1], 0.f);
        unsigned long long a_g = pack2(sBias[grp * 4 + 2], 0.f);
        unsigned long long a_o = pack2(sBias[grp * 4 + 3], 0.f);

        // prime pipeline: chunks 0 and 1 (h rows — ready after last grid barrier)
        if (tid == 0) {
            issue_chunk(mbar0, sIn32,                 gin);
            issue_chunk(mbar1, sIn32 + CHUNK_BYTES,   gin + BB * CHUNKF);
        }

        // x contribution (kk rows 0,1) — overlaps with the first DMA
        {
            const float* xp = strokes + ((size_t)b * TT + t) * 3;
            unsigned long long vx0 = pack2(xp[0], xp[1]);
            unsigned long long vx1 = pack2(xp[2], 0.f);
            const ulonglong2* w0 = (const ulonglong2*)(sWp + grp * 8);
            const ulonglong2* w1 = (const ulonglong2*)(sWp + 32 + grp * 8);
            ulonglong2 wA0 = w0[0], wA1 = w0[1], wB0 = w1[0], wB1 = w1[1];
            ffma2(a_i, vx0, wA0.x); ffma2(a_f, vx0, wA0.y);
            ffma2(a_g, vx0, wA1.x); ffma2(a_o, vx0, wA1.y);
            ffma2(a_i, vx1, wB0.x); ffma2(a_f, vx1, wB0.y);
            ffma2(a_g, vx1, wB1.x); ffma2(a_o, vx1, wB1.y);
        }

        const unsigned int wtarget = (unsigned int)t * GRID;

        for (int c = 0; c < NCHUNK; ++c) {
            const int s = c & 1;
            // global use index of buffer s this step = c>>1; parity = (t + c/2) & 1
            mbar_wait(s ? mbar1 : mbar0, (unsigned int)((t + (c >> 1)) & 1));

            const float* sb = sIn + s * (BB * CHUNKF) + b * CHUNKF;
            // kk row for staged row 64c is 32c+2
            const ulonglong2* wbase =
                (const ulonglong2*)(sWp + (32 * c + 2) * 32 + grp * 8);
#pragma unroll 4
            for (int q = 0; q < 16; ++q) {
                // swizzled 16B load: slot q^bsw holds k-group q for this lane
                ulonglong2 vv = *(const ulonglong2*)(sb + ((q ^ bsw) << 2));
                const ulonglong2* w = wbase + q * 16;           // 2 kk rows per q
                ulonglong2 wA0 = w[0], wA1 = w[1];              // kk   : (i,f),(g,o)
                ulonglong2 wB0 = w[8], wB1 = w[9];              // kk+1
                ffma2(a_i, vv.x, wA0.x); ffma2(a_f, vv.x, wA0.y);
                ffma2(a_g, vv.x, wA1.x); ffma2(a_o, vv.x, wA1.y);
                ffma2(a_i, vv.y, wB0.x); ffma2(a_f, vv.y, wB0.y);
                ffma2(a_g, vv.y, wB1.x); ffma2(a_o, vv.y, wB1.y);
            }
            __syncthreads();           // all lanes done with buffer s
            if (c + 2 < NCHUNK && tid == 0) {
                if (c == 6) {
                    // chunks 8,9 carry w_{t-1}: wait for all CTAs' phase C(t-1)
                    volatile unsigned int* vp = &g_wdone;
                    while (*vp < wtarget) { }
                    __threadfence();
                }
                issue_chunk(s ? mbar1 : mbar0,
                            sIn32 + s * CHUNK_BYTES,
                            gin + (c + 2) * (BB * CHUNKF));
            }
        }

        // =========== Phase B: LSTM pointwise update (1 column / thread) ===========
        {
            float lo, hi;
            unpack2(a_i, lo, hi); float zi = lo + hi;
            unpack2(a_f, lo, hi); float zf = lo + hi;
            unpack2(a_g, lo, hi); float zg = lo + hi;
            unpack2(a_o, lo, hi); float zo = lo + hi;

            float cn = sigf(zf) * creg + sigf(zi) * tanhf(zg);
            float hn = sigf(zo) * tanhf(cn); creg = cn;

            int col = j0 + grp;
            out[((size_t)b * TT + t) * OUT_STRIDE + col] = hn;
            // swizzled global store: k=col -> chunk col>>6, group (col>>2)&15
            int q = (col >> 2) & 15;
            gnext[(col >> 6) * (BB * CHUNKF) + b * CHUNKF +
                  (((q ^ bsw) << 2) | (col & 3))] = hn;
        }

        tgt += GRID;
        grid_barrier(tgt);   // all h_new visible (in out[] and next g_inp buf)

        // =========== Phase C: attention head for batch row bb ===========
        {
            float* orow = out + ((size_t)bb * TT + t) * OUT_STRIDE;

            s_h[tid] = orow[tid];       // BLOCK==HH: coalesced own-row h read
            __syncthreads();

            // y = h @ Wd  (30 outputs, 16-way K split over 480 threads)
            if (tid < 480) {
                int n = tid >> 4, q = tid & 15;
                int k0 = q * 32;
                float p0 = 0.f, p1 = 0.f, p2 = 0.f, p3 = 0.f;
#pragma unroll 4
                for (int k = k0; k < k0 + 32; k += 4) {
                    p0 = fmaf(s_h[k],     sWd[(k)     * 30 + n], p0);
                    p1 = fmaf(s_h[k + 1], sWd[(k + 1) * 30 + n], p1);
                    p2 = fmaf(s_h[k + 2], sWd[(k + 2) * 30 + n], p2);
                    p3 = fmaf(s_h[k + 3], sWd[(k + 3) * 30 + n], p3);
                }
                s_yp[tid] = (p0 + p1) + (p2 + p3);
            }
            __syncthreads();
            if (tid < 30) {
                float s = 0.f;
#pragma unroll
                for (int q = 0; q < 16; ++q) s += s_yp[tid * 16 + q];
                s_y[tid] = __expf(s + s_bd[tid]);
            }
            __syncthreads();
            if (tid < MM) {
                float ka = g_kappa[bb * MM + tid] + s_y[20 + tid];
                g_kappa[bb * MM + tid] = ka;
                s_ka[tid] = ka;
                s_a[tid]  = s_y[tid];
                s_be[tid] = s_y[10 + tid];
            }
            __syncthreads();

            // phi / wfull over u = 0..128
            if (tid <= UU) {
                float fu = (float)tid;
                float acc = 0.f;
#pragma unroll
                for (int m = 0; m < MM; ++m) {
                    float d = s_ka[m] - fu;
                    acc = fmaf(s_a[m], __expf(-s_be[m] * d * d), acc);
                }
                s_wf[tid] = acc;
            }
            __syncthreads();

            // argmax (first-max tie rule), warp 0
            if (tid < 32) {
                float bv = -3.4e38f; int bi = 0;
                for (int u = tid; u <= UU; u += 32) {
                    float v = s_wf[u];
                    if (v > bv) { bv = v; bi = u; }
                }
                for (int off = 16; off; off >>= 1) {
                    float ov = __shfl_xor_sync(0xffffffffu, bv, off);
                    int   oi = __shfl_xor_sync(0xffffffffu, bi, off);
                    if (ov > bv || (ov == bv && oi < bi)) { bv = ov; bi = oi; }
                }
                if (tid == 0) orow[HH + NW] = (float)bi;
            }

            // w = wfull[:U] @ transcriptions[bb]
            if (tid < NW) {
                float a0 = 0.f, a1 = 0.f, a2 = 0.f, a3 = 0.f;
#pragma unroll 4
                for (int u = 0; u < UU; u += 4) {
                    a0 = fmaf(s_wf[u],     sTr[(u)     * NW + tid], a0);
                    a1 = fmaf(s_wf[u + 1], sTr[(u + 1) * NW + tid], a1);
                    a2 = fmaf(s_wf[u + 2], sTr[(u + 2) * NW + tid], a2);
                    a3 = fmaf(s_wf[u + 3], sTr[(u + 3) * NW + tid], a3);
                }
                float wv = (a0 + a1) + (a2 + a3);
                // swizzled global store for staged k = 512+tid (row owner = bb)
                int k = HH + tid;
                int q = (k >> 2) & 15;
                gnext[(k >> 6) * (BB * CHUNKF) + bb * CHUNKF +
                      (((q ^ (bb & 15)) << 2) | (k & 3))] = wv;
                orow[HH + tid] = wv;
            }

            __syncthreads();
            if (tid == 0) {            // signal w_t ready (consumed at chunk 8 of t+1)
                __threadfence();
                atomicAdd(&g_wdone, 1u);
            }
        }
    }
}

// ---------------- launch ----------------
extern "C" void kernel_launch(void* const* d_in, const int* in_sizes, int n_in,
                              void* d_out, int out_size) {
    const float* strokes = (const float*)d_in[0];
    const float* trans   = (const float*)d_in[1];
    // d_in[2] = enumerated (0..128) -- recomputed on the fly
    const float* Wx      = (const float*)d_in[3];
    const float* Wh      = (const float*)d_in[4];
    const float* bvec    = (const float*)d_in[5];
    const float* Wd      = (const float*)d_in[6];
    const float* bd      = (const float*)d_in[7];
    float* out = (float*)d_out;

    cudaFuncSetAttribute(rnn_persistent_kernel,
                         cudaFuncAttributeMaxDynamicSharedMemorySize, SMEM_BYTES);

    rnn_init_kernel<<<32, 256>>>();
    rnn_persistent_kernel<<<GRID, BLOCK, SMEM_BYTES>>>(strokes, trans, Wx, Wh,
                                                       bvec, Wd, bd, out);
}